// round 4
// baseline (speedup 1.0000x reference)
#include <cuda_runtime.h>
#include <cstdint>

// Problem constants
#define NUM_VERTS 6890
#define NUM_FACES 13776
#define HW (1024 * 1024)
#define NBATCH 16
#define THREADS 256
#define PX_PER_THREAD 4
#define PX_PER_BLOCK (THREADS * PX_PER_THREAD)      // 1024 pixels
#define TILE_FLOATS (PX_PER_BLOCK * 3)              // 3072 floats
#define TILE_BYTES (TILE_FLOATS * 4)                // 12288 B

// Exploits:
//  1. Reference gathers only batch-0 faces/verts, broadcasts (H,W,3) over 16
//     batches -> compute once, TMA-replicate 16x.
//  2. JAX x64 disabled -> index tensors are int32 on device.
//  3. R3 ncu: L1 (69.6%) bound by scattered LDG.32 gather wavefronts.
//     Fix: prep kernel packs per-face vertex attrs into 3x float4 (48B recs,
//     L2-resident 661KB) -> main kernel gathers 3 LDG.128/pixel, single-level.

// Scratch: packed face attrs, g_fattr[f*3+k] = (v_k.x, v_k.y, v_k.z, 0)
__device__ __align__(16) float4 g_fattr[NUM_FACES * 3];

__global__ __launch_bounds__(256) void prep_faces_kernel(
    const float* __restrict__ verts,   // (16, 6890, 3) — batch 0 only
    const int*   __restrict__ faces)   // (13776, 3) int32
{
    const int f = blockIdx.x * blockDim.x + threadIdx.x;
    if (f >= NUM_FACES) return;
#pragma unroll
    for (int k = 0; k < 3; k++) {
        int vi = faces[f * 3 + k];
        vi = (vi < 0 || vi >= NUM_VERTS) ? 0 : vi;
        const float* vp = verts + vi * 3;
        g_fattr[f * 3 + k] = make_float4(vp[0], vp[1], vp[2], 0.0f);
    }
}

__global__ __launch_bounds__(THREADS) void uv_render_kernel(
    const int*   __restrict__ pix,     // (1024, 1024) int32
    const float* __restrict__ bary,    // (1024, 1024, 3) fp32
    float* __restrict__ out)           // (16, 1024, 1024, 3) fp32
{
    __shared__ __align__(128) float tile[TILE_FLOATS];   // 12 KB

    const int t  = blockIdx.x * blockDim.x + threadIdx.x;
    const int p0 = t * PX_PER_THREAD;

    // ---- 4 pixel ids: one int4 ----
    const int4 pi = *reinterpret_cast<const int4*>(pix + p0);
    int pf[4] = { pi.x, pi.y, pi.z, pi.w };

    // ---- 12 bary coords: 3x float4 ----
    const float4* b4 = reinterpret_cast<const float4*>(bary + (size_t)p0 * 3);
    float4 bA = b4[0], bB = b4[1], bC = b4[2];
    const float bar[12] = { bA.x, bA.y, bA.z, bA.w,
                            bB.x, bB.y, bB.z, bB.w,
                            bC.x, bC.y, bC.z, bC.w };

    // ---- 12 float4 gathers, all independent (MLP=12 into L2) ----
    float4 va[4][3];
#pragma unroll
    for (int i = 0; i < 4; i++) {
        int f = pf[i];
        f = (f < 0 || f >= NUM_FACES) ? 0 : f;   // bg -> face 0, mask later
        const float4* rec = g_fattr + f * 3;
#pragma unroll
        for (int k = 0; k < 3; k++) va[i][k] = rec[k];
    }

    // ---- weighted sum, mask background ----
    float res[12];
#pragma unroll
    for (int i = 0; i < 4; i++) {
        const float m = (pf[i] >= 0) ? 1.0f : 0.0f;
        float b0 = bar[i * 3 + 0], b1 = bar[i * 3 + 1], b2 = bar[i * 3 + 2];
        res[i * 3 + 0] = (b0 * va[i][0].x + b1 * va[i][1].x + b2 * va[i][2].x) * m;
        res[i * 3 + 1] = (b0 * va[i][0].y + b1 * va[i][1].y + b2 * va[i][2].y) * m;
        res[i * 3 + 2] = (b0 * va[i][0].z + b1 * va[i][1].z + b2 * va[i][2].z) * m;
    }

    // ---- tile to smem (3x STS.128) ----
    {
        float4* t4 = reinterpret_cast<float4*>(tile) + threadIdx.x * 3;
        t4[0] = make_float4(res[0], res[1], res[2],  res[3]);
        t4[1] = make_float4(res[4], res[5], res[6],  res[7]);
        t4[2] = make_float4(res[8], res[9], res[10], res[11]);
    }
    __syncthreads();

    // ---- one thread TMA-bulk-stores the tile to all 16 batch slices ----
    if (threadIdx.x == 0) {
        asm volatile("fence.proxy.async.shared::cta;" ::: "memory");
        uint32_t saddr;
        asm("{ .reg .u64 tmp; cvta.to.shared.u64 tmp, %1; cvt.u32.u64 %0, tmp; }"
            : "=r"(saddr) : "l"(tile));
        const size_t gbase   = (size_t)blockIdx.x * TILE_FLOATS;
        const size_t bstride = (size_t)HW * 3;
#pragma unroll
        for (int n = 0; n < NBATCH; n++) {
            float* dst = out + gbase + (size_t)n * bstride;
            asm volatile(
                "cp.async.bulk.global.shared::cta.bulk_group [%0], [%1], %2;"
                :: "l"(dst), "r"(saddr), "n"(TILE_BYTES) : "memory");
        }
        asm volatile("cp.async.bulk.commit_group;" ::: "memory");
        asm volatile("cp.async.bulk.wait_group 0;" ::: "memory");
    }
}

extern "C" void kernel_launch(void* const* d_in, const int* in_sizes, int n_in,
                              void* d_out, int out_size)
{
    const float* verts = (const float*)d_in[0];
    const int*   faces = (const int*)d_in[1];
    const int*   pix   = (const int*)d_in[2];
    const float* bary  = (const float*)d_in[3];
    float* out = (float*)d_out;

    prep_faces_kernel<<<(NUM_FACES + 255) / 256, 256>>>(verts, faces);
    uv_render_kernel<<<HW / PX_PER_BLOCK, THREADS>>>(pix, bary, out);
}